// round 1
// baseline (speedup 1.0000x reference)
#include <cuda_runtime.h>
#include <math.h>

// ---------------- problem constants ----------------
#define B_N   32
#define R_N   64
#define L_N   4096         // R*R
#define C_N   96
#define NH_N  3
#define HD_N  32
#define G_N   8
#define GG_N  64           // G*G
#define NW_N  2048         // B * (R/G)^2
#define T_N   131072       // NW * GG  (= B*L)
#define HID_N 384

#define OUT0_ELEMS (T_N * C_N)              // 12582912
#define ATTN_ELEMS (NW_N * NH_N * GG_N * GG_N)  // 25165824

__device__ __constant__ float kScale = 0.17677669529663687f; // 32^-0.5

// ---------------- scratch (static device globals: allowed) ----------------
__device__ float g_h[T_N * C_N];          // LN1-windowed; reused as LN2 output
__device__ float g_qkv[T_N * 3 * C_N];    // qkv, window-major rows
__device__ float g_o[T_N * C_N];          // attn@v + lepe, window-major
__device__ float g_x1[T_N * C_N];         // x + proj (token-major)
__device__ float g_hid[T_N * HID_N];      // mlp hidden

// window-major token index -> token-major (B,L) flat row
__device__ __forceinline__ int win2tok(int m) {
    int w = m >> 6, t = m & 63;
    int b = w >> 6, rem = w & 63;
    int hy = rem >> 3, wx = rem & 7;
    int gy = t >> 3,  gx = t & 7;
    return b * L_N + (hy * 8 + gy) * 64 + (wx * 8 + gx);
}

// ---------------- LayerNorm (one warp per token, C=96 = 3 per lane) -------
template<bool GATHER>
__global__ void ln_kernel(const float* __restrict__ x,
                          const float* __restrict__ g,
                          const float* __restrict__ b,
                          float* __restrict__ out) {
    int warp = (blockIdx.x * blockDim.x + threadIdx.x) >> 5;
    int lane = threadIdx.x & 31;
    if (warp >= T_N) return;
    int inrow = GATHER ? win2tok(warp) : warp;
    const float* xr = x + (size_t)inrow * C_N;
    float v0 = xr[lane], v1 = xr[lane + 32], v2 = xr[lane + 64];
    float s = v0 + v1 + v2;
    #pragma unroll
    for (int o = 16; o; o >>= 1) s += __shfl_xor_sync(~0u, s, o);
    float m = s * (1.f / 96.f);
    float d0 = v0 - m, d1 = v1 - m, d2 = v2 - m;
    float q = d0 * d0 + d1 * d1 + d2 * d2;
    #pragma unroll
    for (int o = 16; o; o >>= 1) q += __shfl_xor_sync(~0u, q, o);
    float r = rsqrtf(q * (1.f / 96.f) + 1e-5f);
    float* orow = out + (size_t)warp * C_N;
    orow[lane]      = d0 * r * g[lane]      + b[lane];
    orow[lane + 32] = d1 * r * g[lane + 32] + b[lane + 32];
    orow[lane + 64] = d2 * r * g[lane + 64] + b[lane + 64];
}

// ---------------- generic SGEMM: C[M,N] = A[M,K] @ B[K,N] + bias ----------
// EPI: 0 = bias only; 1 = bias+exact GELU; 2 = bias + res[row]; 
//      3 = bias + res[win2tok(row)] with scattered output row
template<int EPI>
__global__ void sgemm_kernel(int M, int N, int K,
                             const float* __restrict__ A,
                             const float* __restrict__ Bm,
                             const float* __restrict__ bias,
                             const float* __restrict__ res,
                             float* __restrict__ Cout) {
    constexpr int BM = 64, BN = 64, BK = 32;
    __shared__ float As[BK][BM + 1];   // transposed, padded
    __shared__ float Bs[BK][BN];
    int tid = threadIdx.x;             // 256
    int tx = tid & 15, ty = tid >> 4;
    int m0 = blockIdx.y * BM, n0 = blockIdx.x * BN;

    float acc[4][4] = {};
    for (int k0 = 0; k0 < K; k0 += BK) {
        #pragma unroll
        for (int e = 0; e < 8; e++) {
            int idx = e * 256 + tid;
            int kk = idx & 31, mm = idx >> 5;       // coalesced along K
            As[kk][mm] = A[(size_t)(m0 + mm) * K + k0 + kk];
        }
        #pragma unroll
        for (int e = 0; e < 8; e++) {
            int idx = e * 256 + tid;
            int nn = idx & 63, kk = idx >> 6;       // coalesced along N
            int col = n0 + nn;
            Bs[kk][nn] = (col < N) ? Bm[(size_t)(k0 + kk) * N + col] : 0.f;
        }
        __syncthreads();
        #pragma unroll
        for (int k = 0; k < BK; k++) {
            float a[4], bv[4];
            #pragma unroll
            for (int i = 0; i < 4; i++) a[i] = As[k][ty * 4 + i];
            #pragma unroll
            for (int j = 0; j < 4; j++) bv[j] = Bs[k][tx * 4 + j];
            #pragma unroll
            for (int i = 0; i < 4; i++)
                #pragma unroll
                for (int j = 0; j < 4; j++) acc[i][j] += a[i] * bv[j];
        }
        __syncthreads();
    }
    #pragma unroll
    for (int i = 0; i < 4; i++) {
        int row  = m0 + ty * 4 + i;
        int orow = (EPI == 3) ? win2tok(row) : row;
        #pragma unroll
        for (int j = 0; j < 4; j++) {
            int col = n0 + tx * 4 + j;
            if (col < N) {
                float v = acc[i][j] + bias[col];
                if (EPI == 1) v = 0.5f * v * (1.f + erff(v * 0.70710678118f));
                if (EPI == 2 || EPI == 3) v += res[(size_t)orow * N + col];
                Cout[(size_t)orow * N + col] = v;
            }
        }
    }
}

// ---------------- attention + LePE, one block per (window, head) ----------
__global__ void attn_kernel(const float* __restrict__ qkv,
                            const float* __restrict__ wl,
                            const float* __restrict__ bl,
                            float* __restrict__ obuf,
                            float* __restrict__ attn_out) {
    int w = blockIdx.x, h = blockIdx.y;
    __shared__ float Qs[64][33], Ks[64][33], Vs[64][33], Ss[64][65];
    int tid = threadIdx.x;   // 256

    for (int idx = tid; idx < 64 * 32; idx += 256) {
        int t = idx >> 5, d = idx & 31;
        const float* row = qkv + (size_t)(w * 64 + t) * 288 + h * 32 + d;
        Qs[t][d] = row[0];
        Ks[t][d] = row[96];
        Vs[t][d] = row[192];
    }
    __syncthreads();

    // S = (q*scale) @ k^T
    int j  = tid & 63;
    int i0 = tid >> 6;    // 0..3
    #pragma unroll
    for (int r = 0; r < 16; r++) {
        int i = i0 * 16 + r;
        float s = 0.f;
        #pragma unroll
        for (int d = 0; d < 32; d++) s += Qs[i][d] * Ks[j][d];
        Ss[i][j] = s * kScale;
    }
    __syncthreads();

    // softmax rows (8 warps x 8 rows), also emit attention probs output
    int wid = tid >> 5, lane = tid & 31;
    for (int rr = 0; rr < 8; rr++) {
        int i = wid * 8 + rr;
        float a0 = Ss[i][lane], a1 = Ss[i][lane + 32];
        float mx = fmaxf(a0, a1);
        #pragma unroll
        for (int o = 16; o; o >>= 1) mx = fmaxf(mx, __shfl_xor_sync(~0u, mx, o));
        float e0 = __expf(a0 - mx), e1 = __expf(a1 - mx);
        float sm = e0 + e1;
        #pragma unroll
        for (int o = 16; o; o >>= 1) sm += __shfl_xor_sync(~0u, sm, o);
        float inv = 1.f / sm;
        e0 *= inv; e1 *= inv;
        Ss[i][lane] = e0; Ss[i][lane + 32] = e1;
        float* ao = attn_out + ((size_t)(w * 3 + h) * 64 + i) * 64;
        ao[lane] = e0; ao[lane + 32] = e1;
    }
    __syncthreads();

    // O = S@V + LePE(depthwise 3x3 over V image) ; write window-major o
    for (int idx = tid; idx < 64 * 32; idx += 256) {
        int t = idx >> 5, d = idx & 31;
        float o = 0.f;
        #pragma unroll
        for (int jj = 0; jj < 64; jj++) o += Ss[t][jj] * Vs[jj][d];
        int c = h * 32 + d;
        int gy = t >> 3, gx = t & 7;
        float lp = bl[c];
        #pragma unroll
        for (int dy = -1; dy <= 1; dy++) {
            int yy = gy + dy;
            if (yy < 0 || yy > 7) continue;
            #pragma unroll
            for (int dx = -1; dx <= 1; dx++) {
                int xx = gx + dx;
                if (xx < 0 || xx > 7) continue;
                lp += Vs[yy * 8 + xx][d] * wl[c * 9 + (dy + 1) * 3 + (dx + 1)];
            }
        }
        obuf[(size_t)(w * 64 + t) * C_N + c] = o + lp;
    }
}

// ---------------- launch ----------------
extern "C" void kernel_launch(void* const* d_in, const int* in_sizes, int n_in,
                              void* d_out, int out_size) {
    const float* x      = (const float*)d_in[0];
    const float* w_qkv  = (const float*)d_in[1];
    const float* b_qkv  = (const float*)d_in[2];
    const float* w_lepe = (const float*)d_in[3];
    const float* b_lepe = (const float*)d_in[4];
    const float* w_proj = (const float*)d_in[5];
    const float* b_proj = (const float*)d_in[6];
    const float* g1     = (const float*)d_in[7];
    const float* bt1    = (const float*)d_in[8];
    const float* g2     = (const float*)d_in[9];
    const float* bt2    = (const float*)d_in[10];
    const float* w_fc1  = (const float*)d_in[11];
    const float* b_fc1  = (const float*)d_in[12];
    const float* w_fc2  = (const float*)d_in[13];
    const float* b_fc2  = (const float*)d_in[14];

    float* out0 = (float*)d_out;

    float *ph, *pqkv, *po, *px1, *phid;
    cudaGetSymbolAddress((void**)&ph,   g_h);
    cudaGetSymbolAddress((void**)&pqkv, g_qkv);
    cudaGetSymbolAddress((void**)&po,   g_o);
    cudaGetSymbolAddress((void**)&px1,  g_x1);
    cudaGetSymbolAddress((void**)&phid, g_hid);

    // second output (attention probs) lives right after out0 in d_out
    float* attn_out = (out_size >= OUT0_ELEMS + ATTN_ELEMS)
                        ? (out0 + OUT0_ELEMS) : phid;  // fallback: scratch

    // 1. LN1 + window partition gather (window-major rows)
    ln_kernel<true><<<T_N / 8, 256>>>(x, g1, bt1, ph);

    // 2. QKV gemm: (131072 x 96) @ (96 x 288) + bias
    sgemm_kernel<0><<<dim3(5, T_N / 64), 256>>>(T_N, 288, 96, ph, w_qkv, b_qkv, nullptr, pqkv);

    // 3. attention + lepe (+ attn output)
    attn_kernel<<<dim3(NW_N, NH_N), 256>>>(pqkv, w_lepe, b_lepe, po, attn_out);

    // 4. proj gemm + window reverse scatter + residual(x): x1
    sgemm_kernel<3><<<dim3(2, T_N / 64), 256>>>(T_N, 96, 96, po, w_proj, b_proj, x, px1);

    // 5. LN2 (token-major)
    ln_kernel<false><<<T_N / 8, 256>>>(px1, g2, bt2, ph);

    // 6. FC1 + exact GELU
    sgemm_kernel<1><<<dim3(6, T_N / 64), 256>>>(T_N, HID_N, 96, ph, w_fc1, b_fc1, nullptr, phid);

    // 7. FC2 + residual(x1) -> out0
    sgemm_kernel<2><<<dim3(2, T_N / 64), 256>>>(T_N, 96, HID_N, phid, w_fc2, b_fc2, px1, out0);
}

// round 2
// speedup vs baseline: 1.9602x; 1.9602x over previous
#include <cuda_runtime.h>
#include <math.h>

// ---------------- problem constants ----------------
#define B_N   32
#define R_N   64
#define L_N   4096
#define C_N   96
#define NH_N  3
#define HD_N  32
#define G_N   8
#define GG_N  64
#define NW_N  2048
#define T_N   131072
#define HID_N 384

#define OUT0_ELEMS (T_N * C_N)
#define ATTN_ELEMS (NW_N * NH_N * GG_N * GG_N)

__device__ __constant__ float kScale = 0.17677669529663687f; // 32^-0.5

// ---------------- scratch ----------------
__device__ float g_h[T_N * C_N];
__device__ float g_qkv[T_N * 3 * C_N];
__device__ float g_o[T_N * C_N];
__device__ float g_x1[T_N * C_N];
__device__ float g_hid[T_N * HID_N];

__device__ __forceinline__ int win2tok(int m) {
    int w = m >> 6, t = m & 63;
    int b = w >> 6, rem = w & 63;
    int hy = rem >> 3, wx = rem & 7;
    int gy = t >> 3,  gx = t & 7;
    return b * L_N + (hy * 8 + gy) * 64 + (wx * 8 + gx);
}

__device__ __forceinline__ float to_tf32(float x) {
    unsigned u;
    asm("cvt.rna.tf32.f32 %0, %1;" : "=r"(u) : "f"(x));
    return __uint_as_float(u);
}

__device__ __forceinline__ void mma8(float* c, const unsigned* a, const unsigned* b) {
    asm volatile(
        "mma.sync.aligned.m16n8k8.row.col.f32.tf32.tf32.f32 "
        "{%0,%1,%2,%3}, {%4,%5,%6,%7}, {%8,%9}, {%0,%1,%2,%3};\n"
        : "+f"(c[0]), "+f"(c[1]), "+f"(c[2]), "+f"(c[3])
        : "r"(a[0]), "r"(a[1]), "r"(a[2]), "r"(a[3]), "r"(b[0]), "r"(b[1]));
}

// ---------------- LayerNorm (one warp per token) ----------------
template<bool GATHER>
__global__ void ln_kernel(const float* __restrict__ x,
                          const float* __restrict__ g,
                          const float* __restrict__ b,
                          float* __restrict__ out) {
    int warp = (blockIdx.x * blockDim.x + threadIdx.x) >> 5;
    int lane = threadIdx.x & 31;
    if (warp >= T_N) return;
    int inrow = GATHER ? win2tok(warp) : warp;
    const float* xr = x + (size_t)inrow * C_N;
    float v0 = xr[lane], v1 = xr[lane + 32], v2 = xr[lane + 64];
    float s = v0 + v1 + v2;
    #pragma unroll
    for (int o = 16; o; o >>= 1) s += __shfl_xor_sync(~0u, s, o);
    float m = s * (1.f / 96.f);
    float d0 = v0 - m, d1 = v1 - m, d2 = v2 - m;
    float q = d0 * d0 + d1 * d1 + d2 * d2;
    #pragma unroll
    for (int o = 16; o; o >>= 1) q += __shfl_xor_sync(~0u, q, o);
    float r = rsqrtf(q * (1.f / 96.f) + 1e-5f);
    float* orow = out + (size_t)warp * C_N;
    orow[lane]      = d0 * r * g[lane]      + b[lane];
    orow[lane + 32] = d1 * r * g[lane + 32] + b[lane + 32];
    orow[lane + 64] = d2 * r * g[lane + 64] + b[lane + 64];
}

// ---------------- tf32 tensor-core GEMM ----------------
// C[M,N] = A[M,K] @ B[K,N] + bias, with epilogues:
// EPI: 0 bias; 1 bias+GELU; 2 bias+res[row]; 3 bias+res[win2tok(row)]+scatter
template<int EPI>
__global__ __launch_bounds__(256)
void mma_gemm(int M, int N, int K,
              const float* __restrict__ A,
              const float* __restrict__ Bm,
              const float* __restrict__ bias,
              const float* __restrict__ res,
              float* __restrict__ Cout) {
    constexpr int BM = 128, BN = 64, BK = 32;
    __shared__ float As[BM][36];   // stride 36: frag loads bank-conflict-free
    __shared__ float Bs[BK][68];

    int tid  = threadIdx.x;
    int lane = tid & 31, wid = tid >> 5;
    int wm = wid >> 1, wn = wid & 1;            // 4x2 warp grid
    int g  = lane >> 2, tig = lane & 3;
    int m0 = blockIdx.y * BM, n0 = blockIdx.x * BN;

    float acc[2][4][4] = {};                    // [mt][nt][frag]
    float4 ra[4];
    float4 rb[2];

    auto loadA = [&](int k0) {
        #pragma unroll
        for (int e = 0; e < 4; e++) {
            int idx = e * 256 + tid;
            int row = idx >> 3, c4 = (idx & 7) * 4;
            ra[e] = *(const float4*)(A + (size_t)(m0 + row) * K + k0 + c4);
        }
    };
    auto loadB = [&](int k0) {
        #pragma unroll
        for (int e = 0; e < 2; e++) {
            int idx = e * 256 + tid;
            int kk = idx >> 4, c4 = (idx & 15) * 4;
            int col = n0 + c4;
            if (col < N) rb[e] = *(const float4*)(Bm + (size_t)(k0 + kk) * N + col);
            else rb[e] = make_float4(0.f, 0.f, 0.f, 0.f);
        }
    };
    auto storeAB = [&]() {
        #pragma unroll
        for (int e = 0; e < 4; e++) {
            int idx = e * 256 + tid;
            int row = idx >> 3, c = (idx & 7) * 4;
            As[row][c + 0] = to_tf32(ra[e].x);
            As[row][c + 1] = to_tf32(ra[e].y);
            As[row][c + 2] = to_tf32(ra[e].z);
            As[row][c + 3] = to_tf32(ra[e].w);
        }
        #pragma unroll
        for (int e = 0; e < 2; e++) {
            int idx = e * 256 + tid;
            int kk = idx >> 4, c = (idx & 15) * 4;
            Bs[kk][c + 0] = to_tf32(rb[e].x);
            Bs[kk][c + 1] = to_tf32(rb[e].y);
            Bs[kk][c + 2] = to_tf32(rb[e].z);
            Bs[kk][c + 3] = to_tf32(rb[e].w);
        }
    };

    int T = K / BK;
    loadA(0); loadB(0);
    storeAB();
    __syncthreads();

    for (int t = 0; t < T; t++) {
        bool more = (t + 1 < T);
        if (more) { loadA((t + 1) * BK); loadB((t + 1) * BK); }

        #pragma unroll
        for (int ks = 0; ks < 4; ks++) {
            int kb = ks * 8;
            unsigned af[2][4], bf[4][2];
            #pragma unroll
            for (int mt = 0; mt < 2; mt++) {
                int r0 = wm * 32 + mt * 16;
                af[mt][0] = __float_as_uint(As[r0 + g    ][kb + tig    ]);
                af[mt][1] = __float_as_uint(As[r0 + g + 8][kb + tig    ]);
                af[mt][2] = __float_as_uint(As[r0 + g    ][kb + tig + 4]);
                af[mt][3] = __float_as_uint(As[r0 + g + 8][kb + tig + 4]);
            }
            #pragma unroll
            for (int nt = 0; nt < 4; nt++) {
                int c0 = wn * 32 + nt * 8;
                bf[nt][0] = __float_as_uint(Bs[kb + tig    ][c0 + g]);
                bf[nt][1] = __float_as_uint(Bs[kb + tig + 4][c0 + g]);
            }
            #pragma unroll
            for (int mt = 0; mt < 2; mt++)
                #pragma unroll
                for (int nt = 0; nt < 4; nt++)
                    mma8(acc[mt][nt], af[mt], bf[nt]);
        }
        __syncthreads();
        if (more) { storeAB(); __syncthreads(); }
    }

    // epilogue: c0,c1 at (g, tig*2[,+1]); c2,c3 at (g+8, ...)
    #pragma unroll
    for (int mt = 0; mt < 2; mt++) {
        #pragma unroll
        for (int half = 0; half < 2; half++) {
            int row  = m0 + wm * 32 + mt * 16 + g + half * 8;
            int orow = (EPI == 3) ? win2tok(row) : row;
            #pragma unroll
            for (int nt = 0; nt < 4; nt++) {
                int col = n0 + wn * 32 + nt * 8 + tig * 2;
                if (col < N) {
                    float v0 = acc[mt][nt][half * 2 + 0] + bias[col];
                    float v1 = acc[mt][nt][half * 2 + 1] + bias[col + 1];
                    if (EPI == 1) {
                        v0 = 0.5f * v0 * (1.f + erff(v0 * 0.70710678118f));
                        v1 = 0.5f * v1 * (1.f + erff(v1 * 0.70710678118f));
                    }
                    if (EPI == 2 || EPI == 3) {
                        v0 += res[(size_t)orow * N + col];
                        v1 += res[(size_t)orow * N + col + 1];
                    }
                    Cout[(size_t)orow * N + col]     = v0;
                    Cout[(size_t)orow * N + col + 1] = v1;
                }
            }
        }
    }
}

// ---------------- attention + LePE, one block per (window, head) ----------
__global__ __launch_bounds__(256)
void attn_kernel(const float* __restrict__ qkv,
                 const float* __restrict__ wl,
                 const float* __restrict__ bl,
                 float* __restrict__ obuf,
                 float* __restrict__ attn_out) {
    int w = blockIdx.x, h = blockIdx.y;
    __shared__ float Qs[64][33], Ks[64][33], Vs[64][33], Ss[64][65];
    int tid = threadIdx.x;   // 256

    for (int idx = tid; idx < 64 * 32; idx += 256) {
        int t = idx >> 5, d = idx & 31;
        const float* row = qkv + (size_t)(w * 64 + t) * 288 + h * 32 + d;
        Qs[t][d] = row[0];
        Ks[t][d] = row[96];
        Vs[t][d] = row[192];
    }
    __syncthreads();

    // S = (q*scale) @ k^T : 4x4 register tile per thread
    {
        int ty = tid >> 4, tx = tid & 15;
        int i0 = ty * 4, j0 = tx * 4;
        float s[4][4] = {};
        #pragma unroll
        for (int d = 0; d < 32; d++) {
            float qv[4], kv[4];
            #pragma unroll
            for (int i = 0; i < 4; i++) qv[i] = Qs[i0 + i][d];
            #pragma unroll
            for (int j = 0; j < 4; j++) kv[j] = Ks[j0 + j][d];
            #pragma unroll
            for (int i = 0; i < 4; i++)
                #pragma unroll
                for (int j = 0; j < 4; j++) s[i][j] += qv[i] * kv[j];
        }
        #pragma unroll
        for (int i = 0; i < 4; i++)
            #pragma unroll
            for (int j = 0; j < 4; j++)
                Ss[i0 + i][j0 + j] = s[i][j] * kScale;
    }
    __syncthreads();

    // softmax rows (8 warps x 8 rows) + emit attn probs
    int wid = tid >> 5, lane = tid & 31;
    for (int rr = 0; rr < 8; rr++) {
        int i = wid * 8 + rr;
        float a0 = Ss[i][lane], a1 = Ss[i][lane + 32];
        float mx = fmaxf(a0, a1);
        #pragma unroll
        for (int o = 16; o; o >>= 1) mx = fmaxf(mx, __shfl_xor_sync(~0u, mx, o));
        float e0 = __expf(a0 - mx), e1 = __expf(a1 - mx);
        float sm = e0 + e1;
        #pragma unroll
        for (int o = 16; o; o >>= 1) sm += __shfl_xor_sync(~0u, sm, o);
        float inv = 1.f / sm;
        e0 *= inv; e1 *= inv;
        Ss[i][lane] = e0; Ss[i][lane + 32] = e1;
        float* ao = attn_out + ((size_t)(w * 3 + h) * 64 + i) * 64;
        ao[lane] = e0; ao[lane + 32] = e1;
    }
    __syncthreads();

    // O = S@V + LePE : 2x4 register tile per thread
    {
        int dx = tid & 7, ty2 = tid >> 3;
        int t0 = ty2 * 2, d0 = dx * 4;
        float o[2][4] = {};
        #pragma unroll
        for (int jj = 0; jj < 64; jj++) {
            float s0 = Ss[t0][jj], s1 = Ss[t0 + 1][jj];
            float vv[4];
            #pragma unroll
            for (int i = 0; i < 4; i++) vv[i] = Vs[jj][d0 + i];
            #pragma unroll
            for (int i = 0; i < 4; i++) { o[0][i] += s0 * vv[i]; o[1][i] += s1 * vv[i]; }
        }
        #pragma unroll
        for (int ti = 0; ti < 2; ti++) {
            int t = t0 + ti;
            int gy = t >> 3, gx = t & 7;
            #pragma unroll
            for (int i = 0; i < 4; i++) {
                int d = d0 + i, c = h * 32 + d;
                float lp = bl[c];
                #pragma unroll
                for (int dy = -1; dy <= 1; dy++) {
                    int yy = gy + dy;
                    if (yy < 0 || yy > 7) continue;
                    #pragma unroll
                    for (int dxk = -1; dxk <= 1; dxk++) {
                        int xx = gx + dxk;
                        if (xx < 0 || xx > 7) continue;
                        lp += Vs[yy * 8 + xx][d] * wl[c * 9 + (dy + 1) * 3 + (dxk + 1)];
                    }
                }
                obuf[(size_t)(w * 64 + t) * C_N + c] = o[ti][i] + lp;
            }
        }
    }
}

// ---------------- launch ----------------
extern "C" void kernel_launch(void* const* d_in, const int* in_sizes, int n_in,
                              void* d_out, int out_size) {
    const float* x      = (const float*)d_in[0];
    const float* w_qkv  = (const float*)d_in[1];
    const float* b_qkv  = (const float*)d_in[2];
    const float* w_lepe = (const float*)d_in[3];
    const float* b_lepe = (const float*)d_in[4];
    const float* w_proj = (const float*)d_in[5];
    const float* b_proj = (const float*)d_in[6];
    const float* g1     = (const float*)d_in[7];
    const float* bt1    = (const float*)d_in[8];
    const float* g2     = (const float*)d_in[9];
    const float* bt2    = (const float*)d_in[10];
    const float* w_fc1  = (const float*)d_in[11];
    const float* b_fc1  = (const float*)d_in[12];
    const float* w_fc2  = (const float*)d_in[13];
    const float* b_fc2  = (const float*)d_in[14];

    float* out0 = (float*)d_out;

    float *ph, *pqkv, *po, *px1, *phid;
    cudaGetSymbolAddress((void**)&ph,   g_h);
    cudaGetSymbolAddress((void**)&pqkv, g_qkv);
    cudaGetSymbolAddress((void**)&po,   g_o);
    cudaGetSymbolAddress((void**)&px1,  g_x1);
    cudaGetSymbolAddress((void**)&phid, g_hid);

    float* attn_out = (out_size >= OUT0_ELEMS + ATTN_ELEMS)
                        ? (out0 + OUT0_ELEMS) : phid;

    // 1. LN1 + window partition gather
    ln_kernel<true><<<T_N / 8, 256>>>(x, g1, bt1, ph);

    // 2. QKV: (131072 x 96) @ (96 x 288)
    mma_gemm<0><<<dim3(5, T_N / 128), 256>>>(T_N, 288, 96, ph, w_qkv, b_qkv, nullptr, pqkv);

    // 3. attention + lepe
    attn_kernel<<<dim3(NW_N, NH_N), 256>>>(pqkv, w_lepe, b_lepe, po, attn_out);

    // 4. proj + window-reverse scatter + residual(x)
    mma_gemm<3><<<dim3(2, T_N / 128), 256>>>(T_N, 96, 96, po, w_proj, b_proj, x, px1);

    // 5. LN2
    ln_kernel<false><<<T_N / 8, 256>>>(px1, g2, bt2, ph);

    // 6. FC1 + exact GELU
    mma_gemm<1><<<dim3(6, T_N / 128), 256>>>(T_N, HID_N, 96, ph, w_fc1, b_fc1, nullptr, phid);

    // 7. FC2 + residual(x1)
    mma_gemm<2><<<dim3(2, T_N / 128), 256>>>(T_N, 96, HID_N, phid, w_fc2, b_fc2, px1, out0);
}

// round 4
// speedup vs baseline: 2.7343x; 1.3950x over previous
#include <cuda_runtime.h>
#include <cuda_bf16.h>
#include <math.h>

// ---------------- problem constants ----------------
#define B_N   32
#define L_N   4096
#define C_N   96
#define NH_N  3
#define HD_N  32
#define GG_N  64
#define NW_N  2048
#define T_N   131072
#define HID_N 384

#define OUT0_ELEMS (T_N * C_N)
#define ATTN_ELEMS (NW_N * NH_N * GG_N * GG_N)

__device__ __constant__ float kScale = 0.17677669529663687f; // 32^-0.5

// ---------------- scratch ----------------
__device__ float g_qkv[T_N * 3 * C_N];   // window-major qkv
__device__ float g_o[T_N * C_N];         // attn out + lepe, window-major
__device__ float g_x1[T_N * C_N];        // x + proj, token-major
__device__ float g_attn_fb[ATTN_ELEMS];  // fallback sink for attn probs

__device__ __forceinline__ int win2tok(int m) {
    int w = m >> 6, t = m & 63;
    int b = w >> 6, rem = w & 63;
    int hy = rem >> 3, wx = rem & 7;
    int gy = t >> 3,  gx = t & 7;
    return b * L_N + (hy * 8 + gy) * 64 + (wx * 8 + gx);
}

// bf16 m16n8k16 mma, fp32 accumulate
__device__ __forceinline__ void mma16(float* c, const unsigned* a, const unsigned* b) {
    asm volatile(
        "mma.sync.aligned.m16n8k16.row.col.f32.bf16.bf16.f32 "
        "{%0,%1,%2,%3}, {%4,%5,%6,%7}, {%8,%9}, {%0,%1,%2,%3};\n"
        : "+f"(c[0]), "+f"(c[1]), "+f"(c[2]), "+f"(c[3])
        : "r"(a[0]), "r"(a[1]), "r"(a[2]), "r"(a[3]), "r"(b[0]), "r"(b[1]));
}

// warp computes LN of one 96-wide row; writes bf16 into smem row (stride 100)
__device__ __forceinline__ void ln_row_to_smem(const float* __restrict__ xr,
                                               const float* __restrict__ g,
                                               const float* __restrict__ b,
                                               __nv_bfloat16* __restrict__ dst,
                                               int lane) {
    float v0 = xr[lane], v1 = xr[lane + 32], v2 = xr[lane + 64];
    float s = v0 + v1 + v2;
    #pragma unroll
    for (int o = 16; o; o >>= 1) s += __shfl_xor_sync(~0u, s, o);
    float m = s * (1.f / 96.f);
    float d0 = v0 - m, d1 = v1 - m, d2 = v2 - m;
    float q = d0 * d0 + d1 * d1 + d2 * d2;
    #pragma unroll
    for (int o = 16; o; o >>= 1) q += __shfl_xor_sync(~0u, q, o);
    float r = rsqrtf(q * (1.f / 96.f) + 1e-5f);
    dst[lane]      = __float2bfloat16(d0 * r * g[lane]      + b[lane]);
    dst[lane + 32] = __float2bfloat16(d1 * r * g[lane + 32] + b[lane + 32]);
    dst[lane + 64] = __float2bfloat16(d2 * r * g[lane + 64] + b[lane + 64]);
}

// ---------------- one-shot K=96 bf16 GEMM ----------------
// M-tile 128, N-tile 96, no k-loop. A rows are window-major indices.
// LN: fuse LayerNorm into A load (A is token-major x, gathered via win2tok)
// EPI 0: out[row][n0+col] = acc + bias   (qkv)
// EPI 1: out[win2tok(row)][col] = acc + bias + res[win2tok(row)][col] (proj)
template<bool LN, int EPI>
__global__ __launch_bounds__(256)
void gemm96(const float* __restrict__ A, const float* __restrict__ W,
            const float* __restrict__ bias, const float* __restrict__ res,
            const float* __restrict__ lng, const float* __restrict__ lnb,
            float* __restrict__ out, int wld, int old) {
    __shared__ __nv_bfloat16 As[128 * 100];
    __shared__ __nv_bfloat16 Bs[96 * 100];   // transposed [n][k]

    int tid = threadIdx.x, lane = tid & 31, wid = tid >> 5;
    int g = lane >> 2, tig = lane & 3;
    int m0 = blockIdx.y * 128, n0 = blockIdx.x * 96;

    // A tile
    if (LN) {
        #pragma unroll
        for (int r = 0; r < 16; r++) {
            int row = wid * 16 + r;
            ln_row_to_smem(A + (size_t)win2tok(m0 + row) * 96, lng, lnb,
                           As + row * 100, lane);
        }
    } else {
        #pragma unroll
        for (int e = 0; e < 12; e++) {
            int idx = e * 256 + tid;
            int row = idx / 24, c4 = (idx % 24) * 4;
            float4 f = *(const float4*)(A + (size_t)(m0 + row) * 96 + c4);
            __nv_bfloat16* d = As + row * 100 + c4;
            d[0] = __float2bfloat16(f.x); d[1] = __float2bfloat16(f.y);
            d[2] = __float2bfloat16(f.z); d[3] = __float2bfloat16(f.w);
        }
    }
    // B slice, transposed store
    for (int i = tid; i < 96 * 96; i += 256) {
        int k = i / 96, n = i - k * 96;
        Bs[n * 100 + k] = __float2bfloat16(W[(size_t)k * wld + n0 + n]);
    }
    __syncthreads();

    int wm = wid >> 1, wn = wid & 1;
    int mw = wm * 32, nw = wn * 48;
    float acc[2][6][4] = {};
    #pragma unroll
    for (int ks = 0; ks < 6; ks++) {
        int kb = ks * 16;
        unsigned a[2][4], b[6][2];
        #pragma unroll
        for (int mt = 0; mt < 2; mt++) {
            int r = mw + mt * 16;
            a[mt][0] = *(const unsigned*)&As[(r + g)     * 100 + kb + tig * 2];
            a[mt][1] = *(const unsigned*)&As[(r + g + 8) * 100 + kb + tig * 2];
            a[mt][2] = *(const unsigned*)&As[(r + g)     * 100 + kb + 8 + tig * 2];
            a[mt][3] = *(const unsigned*)&As[(r + g + 8) * 100 + kb + 8 + tig * 2];
        }
        #pragma unroll
        for (int nt = 0; nt < 6; nt++) {
            int c = nw + nt * 8 + g;
            b[nt][0] = *(const unsigned*)&Bs[c * 100 + kb + tig * 2];
            b[nt][1] = *(const unsigned*)&Bs[c * 100 + kb + 8 + tig * 2];
        }
        #pragma unroll
        for (int mt = 0; mt < 2; mt++)
            #pragma unroll
            for (int nt = 0; nt < 6; nt++)
                mma16(acc[mt][nt], a[mt], b[nt]);
    }

    #pragma unroll
    for (int mt = 0; mt < 2; mt++) {
        #pragma unroll
        for (int half = 0; half < 2; half++) {
            int row  = m0 + mw + mt * 16 + g + half * 8;
            int orow = (EPI == 1) ? win2tok(row) : row;
            #pragma unroll
            for (int nt = 0; nt < 6; nt++) {
                int col  = nw + nt * 8 + tig * 2;
                int colg = n0 + col;
                float v0 = acc[mt][nt][half * 2 + 0] + bias[colg];
                float v1 = acc[mt][nt][half * 2 + 1] + bias[colg + 1];
                if (EPI == 1) {
                    const float2 r2 = *(const float2*)(res + (size_t)orow * 96 + col);
                    v0 += r2.x; v1 += r2.y;
                }
                *(float2*)(out + (size_t)orow * old + colg) = make_float2(v0, v1);
            }
        }
    }
}

// ---------------- fused MLP: LN2 + FC1 + GELU + FC2 + residual ------------
__global__ __launch_bounds__(256)
void mlp_kernel(const float* __restrict__ x1,
                const float* __restrict__ w1, const float* __restrict__ b1,
                const float* __restrict__ w2, const float* __restrict__ b2,
                const float* __restrict__ lng, const float* __restrict__ lnb,
                float* __restrict__ out) {
    extern __shared__ __nv_bfloat16 sm[];
    __nv_bfloat16* As = sm;                 // 128*100 LN2 activations
    __nv_bfloat16* Hs = sm + 12800;         // 128*100 gelu hidden chunk
    __nv_bfloat16* B1 = sm + 25600;         // 96*100  W1 chunk [n][k]
    __nv_bfloat16* B2 = sm + 35200;         // 96*100  W2 chunk [n][k]

    int tid = threadIdx.x, lane = tid & 31, wid = tid >> 5;
    int g = lane >> 2, tig = lane & 3;
    int m0 = blockIdx.x * 128;
    int wm = wid >> 1, wn = wid & 1;
    int mw = wm * 32, nw = wn * 48;

    #pragma unroll
    for (int r = 0; r < 16; r++) {
        int row = wid * 16 + r;
        ln_row_to_smem(x1 + (size_t)(m0 + row) * 96, lng, lnb, As + row * 100, lane);
    }

    float acc2[2][6][4] = {};
    for (int c = 0; c < 4; c++) {
        for (int i = tid; i < 96 * 96; i += 256) {
            int k = i / 96, n = i - k * 96;
            B1[n * 100 + k] = __float2bfloat16(w1[(size_t)k * HID_N + c * 96 + n]);
        }
        for (int i = tid; i < 96 * 96; i += 256) {
            int k = i / 96, n = i - k * 96;
            B2[n * 100 + k] = __float2bfloat16(w2[(size_t)(c * 96 + k) * 96 + n]);
        }
        __syncthreads();

        // H = As @ B1
        float accH[2][6][4] = {};
        #pragma unroll
        for (int ks = 0; ks < 6; ks++) {
            int kb = ks * 16;
            unsigned a[2][4], b[6][2];
            #pragma unroll
            for (int mt = 0; mt < 2; mt++) {
                int r = mw + mt * 16;
                a[mt][0] = *(const unsigned*)&As[(r + g)     * 100 + kb + tig * 2];
                a[mt][1] = *(const unsigned*)&As[(r + g + 8) * 100 + kb + tig * 2];
                a[mt][2] = *(const unsigned*)&As[(r + g)     * 100 + kb + 8 + tig * 2];
                a[mt][3] = *(const unsigned*)&As[(r + g + 8) * 100 + kb + 8 + tig * 2];
            }
            #pragma unroll
            for (int nt = 0; nt < 6; nt++) {
                int cc = nw + nt * 8 + g;
                b[nt][0] = *(const unsigned*)&B1[cc * 100 + kb + tig * 2];
                b[nt][1] = *(const unsigned*)&B1[cc * 100 + kb + 8 + tig * 2];
            }
            #pragma unroll
            for (int mt = 0; mt < 2; mt++)
                #pragma unroll
                for (int nt = 0; nt < 6; nt++)
                    mma16(accH[mt][nt], a[mt], b[nt]);
        }
        // bias1 + exact GELU, pack bf16 pairs into Hs
        #pragma unroll
        for (int mt = 0; mt < 2; mt++) {
            #pragma unroll
            for (int half = 0; half < 2; half++) {
                int row = mw + mt * 16 + g + half * 8;
                #pragma unroll
                for (int nt = 0; nt < 6; nt++) {
                    int col = nw + nt * 8 + tig * 2;
                    float v0 = accH[mt][nt][half * 2 + 0] + b1[c * 96 + col];
                    float v1 = accH[mt][nt][half * 2 + 1] + b1[c * 96 + col + 1];
                    v0 = 0.5f * v0 * (1.f + erff(v0 * 0.70710678118f));
                    v1 = 0.5f * v1 * (1.f + erff(v1 * 0.70710678118f));
                    *(__nv_bfloat162*)&Hs[row * 100 + col] = __floats2bfloat162_rn(v0, v1);
                }
            }
        }
        __syncthreads();

        // acc2 += Hs @ B2
        #pragma unroll
        for (int ks = 0; ks < 6; ks++) {
            int kb = ks * 16;
            unsigned a[2][4], b[6][2];
            #pragma unroll
            for (int mt = 0; mt < 2; mt++) {
                int r = mw + mt * 16;
                a[mt][0] = *(const unsigned*)&Hs[(r + g)     * 100 + kb + tig * 2];
                a[mt][1] = *(const unsigned*)&Hs[(r + g + 8) * 100 + kb + tig * 2];
                a[mt][2] = *(const unsigned*)&Hs[(r + g)     * 100 + kb + 8 + tig * 2];
                a[mt][3] = *(const unsigned*)&Hs[(r + g + 8) * 100 + kb + 8 + tig * 2];
            }
            #pragma unroll
            for (int nt = 0; nt < 6; nt++) {
                int cc = nw + nt * 8 + g;
                b[nt][0] = *(const unsigned*)&B2[cc * 100 + kb + tig * 2];
                b[nt][1] = *(const unsigned*)&B2[cc * 100 + kb + 8 + tig * 2];
            }
            #pragma unroll
            for (int mt = 0; mt < 2; mt++)
                #pragma unroll
                for (int nt = 0; nt < 6; nt++)
                    mma16(acc2[mt][nt], a[mt], b[nt]);
        }
        __syncthreads();
    }

    // epilogue: + bias2 + residual(x1)
    #pragma unroll
    for (int mt = 0; mt < 2; mt++) {
        #pragma unroll
        for (int half = 0; half < 2; half++) {
            int row = m0 + mw + mt * 16 + g + half * 8;
            #pragma unroll
            for (int nt = 0; nt < 6; nt++) {
                int col = nw + nt * 8 + tig * 2;
                const float2 r2 = *(const float2*)(x1 + (size_t)row * 96 + col);
                float v0 = acc2[mt][nt][half * 2 + 0] + b2[col]     + r2.x;
                float v1 = acc2[mt][nt][half * 2 + 1] + b2[col + 1] + r2.y;
                *(float2*)(out + (size_t)row * 96 + col) = make_float2(v0, v1);
            }
        }
    }
}

// ---------------- attention + LePE, one block per (window, head) ----------
__global__ __launch_bounds__(256)
void attn_kernel(const float* __restrict__ qkv,
                 const float* __restrict__ wl,
                 const float* __restrict__ bl,
                 float* __restrict__ obuf,
                 float* __restrict__ attn_out) {
    int w = blockIdx.x, h = blockIdx.y;
    __shared__ float Qs[64][33], Ks[64][33], Vs[64][33], Ss[64][65];
    int tid = threadIdx.x;

    for (int idx = tid; idx < 64 * 32; idx += 256) {
        int t = idx >> 5, d = idx & 31;
        const float* row = qkv + (size_t)(w * 64 + t) * 288 + h * 32 + d;
        Qs[t][d] = row[0];
        Ks[t][d] = row[96];
        Vs[t][d] = row[192];
    }
    __syncthreads();

    {
        int ty = tid >> 4, tx = tid & 15;
        int i0 = ty * 4, j0 = tx * 4;
        float s[4][4] = {};
        #pragma unroll
        for (int d = 0; d < 32; d++) {
            float qv[4], kv[4];
            #pragma unroll
            for (int i = 0; i < 4; i++) qv[i] = Qs[i0 + i][d];
            #pragma unroll
            for (int j = 0; j < 4; j++) kv[j] = Ks[j0 + j][d];
            #pragma unroll
            for (int i = 0; i < 4; i++)
                #pragma unroll
                for (int j = 0; j < 4; j++) s[i][j] += qv[i] * kv[j];
        }
        #pragma unroll
        for (int i = 0; i < 4; i++)
            #pragma unroll
            for (int j = 0; j < 4; j++)
                Ss[i0 + i][j0 + j] = s[i][j] * kScale;
    }
    __syncthreads();

    int wid = tid >> 5, lane = tid & 31;
    for (int rr = 0; rr < 8; rr++) {
        int i = wid * 8 + rr;
        float a0 = Ss[i][lane], a1 = Ss[i][lane + 32];
        float mx = fmaxf(a0, a1);
        #pragma unroll
        for (int o = 16; o; o >>= 1) mx = fmaxf(mx, __shfl_xor_sync(~0u, mx, o));
        float e0 = __expf(a0 - mx), e1 = __expf(a1 - mx);
        float sm = e0 + e1;
        #pragma unroll
        for (int o = 16; o; o >>= 1) sm += __shfl_xor_sync(~0u, sm, o);
        float inv = 1.f / sm;
        e0 *= inv; e1 *= inv;
        Ss[i][lane] = e0; Ss[i][lane + 32] = e1;
        float* ao = attn_out + ((size_t)(w * 3 + h) * 64 + i) * 64;
        ao[lane] = e0; ao[lane + 32] = e1;
    }
    __syncthreads();

    {
        int dx = tid & 7, ty2 = tid >> 3;
        int t0 = ty2 * 2, d0 = dx * 4;
        float o[2][4] = {};
        #pragma unroll
        for (int jj = 0; jj < 64; jj++) {
            float s0 = Ss[t0][jj], s1 = Ss[t0 + 1][jj];
            float vv[4];
            #pragma unroll
            for (int i = 0; i < 4; i++) vv[i] = Vs[jj][d0 + i];
            #pragma unroll
            for (int i = 0; i < 4; i++) { o[0][i] += s0 * vv[i]; o[1][i] += s1 * vv[i]; }
        }
        #pragma unroll
        for (int ti = 0; ti < 2; ti++) {
            int t = t0 + ti;
            int gy = t >> 3, gx = t & 7;
            #pragma unroll
            for (int i = 0; i < 4; i++) {
                int d = d0 + i, c = h * 32 + d;
                float lp = bl[c];
                #pragma unroll
                for (int dy = -1; dy <= 1; dy++) {
                    int yy = gy + dy;
                    if (yy < 0 || yy > 7) continue;
                    #pragma unroll
                    for (int dxk = -1; dxk <= 1; dxk++) {
                        int xx = gx + dxk;
                        if (xx < 0 || xx > 7) continue;
                        lp += Vs[yy * 8 + xx][d] * wl[c * 9 + (dy + 1) * 3 + (dxk + 1)];
                    }
                }
                obuf[(size_t)(w * 64 + t) * C_N + c] = o[ti][i] + lp;
            }
        }
    }
}

// ---------------- launch ----------------
extern "C" void kernel_launch(void* const* d_in, const int* in_sizes, int n_in,
                              void* d_out, int out_size) {
    const float* x      = (const float*)d_in[0];
    const float* w_qkv  = (const float*)d_in[1];
    const float* b_qkv  = (const float*)d_in[2];
    const float* w_lepe = (const float*)d_in[3];
    const float* b_lepe = (const float*)d_in[4];
    const float* w_proj = (const float*)d_in[5];
    const float* b_proj = (const float*)d_in[6];
    const float* g1     = (const float*)d_in[7];
    const float* bt1    = (const float*)d_in[8];
    const float* g2     = (const float*)d_in[9];
    const float* bt2    = (const float*)d_in[10];
    const float* w_fc1  = (const float*)d_in[11];
    const float* b_fc1  = (const float*)d_in[12];
    const float* w_fc2  = (const float*)d_in[13];
    const float* b_fc2  = (const float*)d_in[14];

    float* out0 = (float*)d_out;

    float *pqkv, *po, *px1, *pfb;
    cudaGetSymbolAddress((void**)&pqkv, g_qkv);
    cudaGetSymbolAddress((void**)&po,   g_o);
    cudaGetSymbolAddress((void**)&px1,  g_x1);
    cudaGetSymbolAddress((void**)&pfb,  g_attn_fb);

    float* attn_out = (out_size >= OUT0_ELEMS + ATTN_ELEMS)
                        ? (out0 + OUT0_ELEMS) : pfb;

    // opt-in smem for the fused MLP (idempotent; no static guards)
    cudaFuncSetAttribute(mlp_kernel,
                         cudaFuncAttributeMaxDynamicSharedMemorySize, 89600);

    // 1. LN1 + QKV (one-shot bf16 mma, LN fused into A load)
    gemm96<true, 0><<<dim3(3, T_N / 128), 256>>>(
        x, w_qkv, b_qkv, nullptr, g1, bt1, pqkv, 288, 288);

    // 2. attention + lepe (+ attn probs)
    attn_kernel<<<dim3(NW_N, NH_N), 256>>>(pqkv, w_lepe, b_lepe, po, attn_out);

    // 3. proj + window-reverse scatter + residual(x) -> x1
    gemm96<false, 1><<<dim3(1, T_N / 128), 256>>>(
        po, w_proj, b_proj, x, nullptr, nullptr, px1, 96, 96);

    // 4. fused MLP: LN2 + FC1 + GELU + FC2 + residual -> out
    mlp_kernel<<<T_N / 128, 256, 89600>>>(px1, w_fc1, b_fc1, w_fc2, b_fc2,
                                          g2, bt2, out0);
}

// round 5
// speedup vs baseline: 3.7424x; 1.3687x over previous
#include <cuda_runtime.h>
#include <cuda_bf16.h>
#include <math.h>

// ---------------- problem constants ----------------
#define B_N   32
#define L_N   4096
#define C_N   96
#define NH_N  3
#define HD_N  32
#define GG_N  64
#define NW_N  2048
#define T_N   131072
#define HID_N 384

#define OUT0_ELEMS (T_N * C_N)
#define ATTN_ELEMS (NW_N * NH_N * GG_N * GG_N)

__device__ __constant__ float kScale = 0.17677669529663687f; // 32^-0.5

// ---------------- scratch ----------------
__device__ float g_qkv[T_N * 3 * C_N];   // window-major qkv
__device__ float g_o[T_N * C_N];         // attn out + lepe, window-major
__device__ float g_x1[T_N * C_N];        // x + proj, token-major
__device__ float g_attn_fb[ATTN_ELEMS];  // fallback sink for attn probs

// precomputed bf16 weights, [n][k] layout, k padded to 100
__device__ __nv_bfloat16 g_wqkv_bf[288 * 100];
__device__ __nv_bfloat16 g_wproj_bf[96 * 100];
__device__ __nv_bfloat16 g_w1_bf[384 * 100];
__device__ __nv_bfloat16 g_w2_bf[4 * 96 * 100];  // [chunk][n][k]

#define QKV_E  (288 * 96)
#define PROJ_E (96 * 96)
#define W1_E   (384 * 96)
#define W2_E   (4 * 96 * 96)

__global__ void prep_weights(const float* __restrict__ wqkv,
                             const float* __restrict__ wproj,
                             const float* __restrict__ w1,
                             const float* __restrict__ w2) {
    int i = blockIdx.x * 256 + threadIdx.x;
    if (i < QKV_E) {
        int n = i / 96, k = i - n * 96;
        g_wqkv_bf[n * 100 + k] = __float2bfloat16(wqkv[(size_t)k * 288 + n]);
        return;
    }
    i -= QKV_E;
    if (i < PROJ_E) {
        int n = i / 96, k = i - n * 96;
        g_wproj_bf[n * 100 + k] = __float2bfloat16(wproj[(size_t)k * 96 + n]);
        return;
    }
    i -= PROJ_E;
    if (i < W1_E) {
        int n = i / 96, k = i - n * 96;
        g_w1_bf[n * 100 + k] = __float2bfloat16(w1[(size_t)k * 384 + n]);
        return;
    }
    i -= W1_E;
    if (i < W2_E) {
        int c = i / 9216, r = i - c * 9216;
        int n = r / 96, k = r - n * 96;
        g_w2_bf[c * 9600 + n * 100 + k] =
            __float2bfloat16(w2[(size_t)(c * 96 + k) * 96 + n]);
    }
}

__device__ __forceinline__ int win2tok(int m) {
    int w = m >> 6, t = m & 63;
    int b = w >> 6, rem = w & 63;
    int hy = rem >> 3, wx = rem & 7;
    int gy = t >> 3,  gx = t & 7;
    return b * L_N + (hy * 8 + gy) * 64 + (wx * 8 + gx);
}

// bf16 m16n8k16 mma, fp32 accumulate
__device__ __forceinline__ void mma16(float* c, const unsigned* a, const unsigned* b) {
    asm volatile(
        "mma.sync.aligned.m16n8k16.row.col.f32.bf16.bf16.f32 "
        "{%0,%1,%2,%3}, {%4,%5,%6,%7}, {%8,%9}, {%0,%1,%2,%3};\n"
        : "+f"(c[0]), "+f"(c[1]), "+f"(c[2]), "+f"(c[3])
        : "r"(a[0]), "r"(a[1]), "r"(a[2]), "r"(a[3]), "r"(b[0]), "r"(b[1]));
}

// warp computes LN of one 96-wide row; writes bf16 into smem row (stride 100)
__device__ __forceinline__ void ln_row_to_smem(const float* __restrict__ xr,
                                               const float* __restrict__ g,
                                               const float* __restrict__ b,
                                               __nv_bfloat16* __restrict__ dst,
                                               int lane) {
    float v0 = xr[lane], v1 = xr[lane + 32], v2 = xr[lane + 64];
    float s = v0 + v1 + v2;
    #pragma unroll
    for (int o = 16; o; o >>= 1) s += __shfl_xor_sync(~0u, s, o);
    float m = s * (1.f / 96.f);
    float d0 = v0 - m, d1 = v1 - m, d2 = v2 - m;
    float q = d0 * d0 + d1 * d1 + d2 * d2;
    #pragma unroll
    for (int o = 16; o; o >>= 1) q += __shfl_xor_sync(~0u, q, o);
    float r = rsqrtf(q * (1.f / 96.f) + 1e-5f);
    dst[lane]      = __float2bfloat16(d0 * r * g[lane]      + b[lane]);
    dst[lane + 32] = __float2bfloat16(d1 * r * g[lane + 32] + b[lane + 32]);
    dst[lane + 64] = __float2bfloat16(d2 * r * g[lane + 64] + b[lane + 64]);
}

// ---------------- one-shot K=96 bf16 GEMM ----------------
// Wbf: precomputed [n][k] bf16, k-stride 100; this block uses rows n0..n0+95.
// EPI 0: out[row][n0+col] = acc + bias (qkv); EPI 1: scatter + residual (proj)
template<bool LN, int EPI>
__global__ __launch_bounds__(256)
void gemm96(const float* __restrict__ A, const __nv_bfloat16* __restrict__ Wbf,
            const float* __restrict__ bias, const float* __restrict__ res,
            const float* __restrict__ lng, const float* __restrict__ lnb,
            float* __restrict__ out, int old) {
    __shared__ __nv_bfloat16 As[128 * 100];
    __shared__ __nv_bfloat16 Bs[96 * 100];   // [n][k]

    int tid = threadIdx.x, lane = tid & 31, wid = tid >> 5;
    int g = lane >> 2, tig = lane & 3;
    int m0 = blockIdx.y * 128, n0 = blockIdx.x * 96;

    // A tile
    if (LN) {
        #pragma unroll
        for (int r = 0; r < 16; r++) {
            int row = wid * 16 + r;
            ln_row_to_smem(A + (size_t)win2tok(m0 + row) * 96, lng, lnb,
                           As + row * 100, lane);
        }
    } else {
        #pragma unroll
        for (int e = 0; e < 12; e++) {
            int idx = e * 256 + tid;
            int row = idx / 24, c4 = (idx % 24) * 4;
            float4 f = *(const float4*)(A + (size_t)(m0 + row) * 96 + c4);
            __nv_bfloat16* d = As + row * 100 + c4;
            d[0] = __float2bfloat16(f.x); d[1] = __float2bfloat16(f.y);
            d[2] = __float2bfloat16(f.z); d[3] = __float2bfloat16(f.w);
        }
    }
    // B slice: contiguous vector copy of precomputed bf16 (9600 elems)
    {
        const int4* src = (const int4*)(Wbf + (size_t)n0 * 100);
        int4* dst = (int4*)Bs;
        #pragma unroll
        for (int e = 0; e < 5; e++) {
            int i = e * 256 + tid;
            if (i < 1200) dst[i] = src[i];
        }
    }
    __syncthreads();

    int wm = wid >> 1, wn = wid & 1;
    int mw = wm * 32, nw = wn * 48;
    float acc[2][6][4] = {};
    #pragma unroll
    for (int ks = 0; ks < 6; ks++) {
        int kb = ks * 16;
        unsigned a[2][4], b[6][2];
        #pragma unroll
        for (int mt = 0; mt < 2; mt++) {
            int r = mw + mt * 16;
            a[mt][0] = *(const unsigned*)&As[(r + g)     * 100 + kb + tig * 2];
            a[mt][1] = *(const unsigned*)&As[(r + g + 8) * 100 + kb + tig * 2];
            a[mt][2] = *(const unsigned*)&As[(r + g)     * 100 + kb + 8 + tig * 2];
            a[mt][3] = *(const unsigned*)&As[(r + g + 8) * 100 + kb + 8 + tig * 2];
        }
        #pragma unroll
        for (int nt = 0; nt < 6; nt++) {
            int c = nw + nt * 8 + g;
            b[nt][0] = *(const unsigned*)&Bs[c * 100 + kb + tig * 2];
            b[nt][1] = *(const unsigned*)&Bs[c * 100 + kb + 8 + tig * 2];
        }
        #pragma unroll
        for (int mt = 0; mt < 2; mt++)
            #pragma unroll
            for (int nt = 0; nt < 6; nt++)
                mma16(acc[mt][nt], a[mt], b[nt]);
    }

    #pragma unroll
    for (int mt = 0; mt < 2; mt++) {
        #pragma unroll
        for (int half = 0; half < 2; half++) {
            int row  = m0 + mw + mt * 16 + g + half * 8;
            int orow = (EPI == 1) ? win2tok(row) : row;
            #pragma unroll
            for (int nt = 0; nt < 6; nt++) {
                int col  = nw + nt * 8 + tig * 2;
                int colg = n0 + col;
                float v0 = acc[mt][nt][half * 2 + 0] + bias[colg];
                float v1 = acc[mt][nt][half * 2 + 1] + bias[colg + 1];
                if (EPI == 1) {
                    const float2 r2 = *(const float2*)(res + (size_t)orow * 96 + col);
                    v0 += r2.x; v1 += r2.y;
                }
                *(float2*)(out + (size_t)orow * old + colg) = make_float2(v0, v1);
            }
        }
    }
}

// ---------------- fused MLP: LN2 + FC1 + GELU + FC2 + residual ------------
__global__ __launch_bounds__(256)
void mlp_kernel(const float* __restrict__ x1,
                const float* __restrict__ b1, const float* __restrict__ b2,
                const float* __restrict__ lng, const float* __restrict__ lnb,
                float* __restrict__ out) {
    extern __shared__ __nv_bfloat16 sm[];
    __nv_bfloat16* As = sm;                 // 128*100 LN2 activations
    __nv_bfloat16* Hs = sm + 12800;         // 128*100 gelu hidden chunk
    __nv_bfloat16* B1 = sm + 25600;         // 96*100  W1 chunk [n][k]
    __nv_bfloat16* B2 = sm + 35200;         // 96*100  W2 chunk [n][k]

    int tid = threadIdx.x, lane = tid & 31, wid = tid >> 5;
    int g = lane >> 2, tig = lane & 3;
    int m0 = blockIdx.x * 128;
    int wm = wid >> 1, wn = wid & 1;
    int mw = wm * 32, nw = wn * 48;

    #pragma unroll
    for (int r = 0; r < 16; r++) {
        int row = wid * 16 + r;
        ln_row_to_smem(x1 + (size_t)(m0 + row) * 96, lng, lnb, As + row * 100, lane);
    }

    float acc2[2][6][4] = {};
    for (int c = 0; c < 4; c++) {
        // contiguous vector copies of precomputed bf16 weight chunks
        {
            const int4* s1 = (const int4*)(g_w1_bf + (size_t)c * 9600);
            const int4* s2 = (const int4*)(g_w2_bf + (size_t)c * 9600);
            int4* d1 = (int4*)B1;
            int4* d2 = (int4*)B2;
            #pragma unroll
            for (int e = 0; e < 5; e++) {
                int i = e * 256 + tid;
                if (i < 1200) { d1[i] = s1[i]; d2[i] = s2[i]; }
            }
        }
        __syncthreads();

        // H = As @ B1
        float accH[2][6][4] = {};
        #pragma unroll
        for (int ks = 0; ks < 6; ks++) {
            int kb = ks * 16;
            unsigned a[2][4], b[6][2];
            #pragma unroll
            for (int mt = 0; mt < 2; mt++) {
                int r = mw + mt * 16;
                a[mt][0] = *(const unsigned*)&As[(r + g)     * 100 + kb + tig * 2];
                a[mt][1] = *(const unsigned*)&As[(r + g + 8) * 100 + kb + tig * 2];
                a[mt][2] = *(const unsigned*)&As[(r + g)     * 100 + kb + 8 + tig * 2];
                a[mt][3] = *(const unsigned*)&As[(r + g + 8) * 100 + kb + 8 + tig * 2];
            }
            #pragma unroll
            for (int nt = 0; nt < 6; nt++) {
                int cc = nw + nt * 8 + g;
                b[nt][0] = *(const unsigned*)&B1[cc * 100 + kb + tig * 2];
                b[nt][1] = *(const unsigned*)&B1[cc * 100 + kb + 8 + tig * 2];
            }
            #pragma unroll
            for (int mt = 0; mt < 2; mt++)
                #pragma unroll
                for (int nt = 0; nt < 6; nt++)
                    mma16(accH[mt][nt], a[mt], b[nt]);
        }
        // bias1 + exact GELU, pack bf16 pairs into Hs
        #pragma unroll
        for (int mt = 0; mt < 2; mt++) {
            #pragma unroll
            for (int half = 0; half < 2; half++) {
                int row = mw + mt * 16 + g + half * 8;
                #pragma unroll
                for (int nt = 0; nt < 6; nt++) {
                    int col = nw + nt * 8 + tig * 2;
                    float v0 = accH[mt][nt][half * 2 + 0] + b1[c * 96 + col];
                    float v1 = accH[mt][nt][half * 2 + 1] + b1[c * 96 + col + 1];
                    v0 = 0.5f * v0 * (1.f + erff(v0 * 0.70710678118f));
                    v1 = 0.5f * v1 * (1.f + erff(v1 * 0.70710678118f));
                    *(__nv_bfloat162*)&Hs[row * 100 + col] = __floats2bfloat162_rn(v0, v1);
                }
            }
        }
        __syncthreads();

        // acc2 += Hs @ B2
        #pragma unroll
        for (int ks = 0; ks < 6; ks++) {
            int kb = ks * 16;
            unsigned a[2][4], b[6][2];
            #pragma unroll
            for (int mt = 0; mt < 2; mt++) {
                int r = mw + mt * 16;
                a[mt][0] = *(const unsigned*)&Hs[(r + g)     * 100 + kb + tig * 2];
                a[mt][1] = *(const unsigned*)&Hs[(r + g + 8) * 100 + kb + tig * 2];
                a[mt][2] = *(const unsigned*)&Hs[(r + g)     * 100 + kb + 8 + tig * 2];
                a[mt][3] = *(const unsigned*)&Hs[(r + g + 8) * 100 + kb + 8 + tig * 2];
            }
            #pragma unroll
            for (int nt = 0; nt < 6; nt++) {
                int cc = nw + nt * 8 + g;
                b[nt][0] = *(const unsigned*)&B2[cc * 100 + kb + tig * 2];
                b[nt][1] = *(const unsigned*)&B2[cc * 100 + kb + 8 + tig * 2];
            }
            #pragma unroll
            for (int mt = 0; mt < 2; mt++)
                #pragma unroll
                for (int nt = 0; nt < 6; nt++)
                    mma16(acc2[mt][nt], a[mt], b[nt]);
        }
        __syncthreads();
    }

    // epilogue: + bias2 + residual(x1)
    #pragma unroll
    for (int mt = 0; mt < 2; mt++) {
        #pragma unroll
        for (int half = 0; half < 2; half++) {
            int row = m0 + mw + mt * 16 + g + half * 8;
            #pragma unroll
            for (int nt = 0; nt < 6; nt++) {
                int col = nw + nt * 8 + tig * 2;
                const float2 r2 = *(const float2*)(x1 + (size_t)row * 96 + col);
                float v0 = acc2[mt][nt][half * 2 + 0] + b2[col]     + r2.x;
                float v1 = acc2[mt][nt][half * 2 + 1] + b2[col + 1] + r2.y;
                *(float2*)(out + (size_t)row * 96 + col) = make_float2(v0, v1);
            }
        }
    }
}

// ---------------- attention + LePE (bf16 mma), block per (window, head) ----
__global__ __launch_bounds__(256)
void attn_kernel(const float* __restrict__ qkv,
                 const float* __restrict__ wl,
                 const float* __restrict__ bl,
                 float* __restrict__ obuf,
                 float* __restrict__ attn_out) {
    int w = blockIdx.x, h = blockIdx.y;
    __shared__ __nv_bfloat16 Qs[64 * 40], Ks[64 * 40];  // [t][d], stride 40
    __shared__ __nv_bfloat16 Vt[32 * 72];               // [d][t], stride 72
    __shared__ __nv_bfloat16 Ps[64 * 72];               // [t][j], stride 72
    __shared__ float Ss[64][65];
    int tid = threadIdx.x, lane = tid & 31, wid = tid >> 5;
    int g = lane >> 2, tig = lane & 3;

    for (int idx = tid; idx < 2048; idx += 256) {
        int t = idx >> 5, d = idx & 31;
        const float* row = qkv + (size_t)(w * 64 + t) * 288 + h * 32 + d;
        Qs[t * 40 + d] = __float2bfloat16(row[0] * kScale);
        Ks[t * 40 + d] = __float2bfloat16(row[96]);
        Vt[d * 72 + t] = __float2bfloat16(row[192]);
    }
    __syncthreads();

    // S = Qscaled @ K^T : warp computes 16 rows x 32 cols
    {
        int mw = (wid >> 1) * 16, nw = (wid & 1) * 32;
        float acc[4][4] = {};
        #pragma unroll
        for (int ks = 0; ks < 2; ks++) {
            int kb = ks * 16;
            unsigned a[4];
            a[0] = *(const unsigned*)&Qs[(mw + g)     * 40 + kb + tig * 2];
            a[1] = *(const unsigned*)&Qs[(mw + g + 8) * 40 + kb + tig * 2];
            a[2] = *(const unsigned*)&Qs[(mw + g)     * 40 + kb + 8 + tig * 2];
            a[3] = *(const unsigned*)&Qs[(mw + g + 8) * 40 + kb + 8 + tig * 2];
            #pragma unroll
            for (int nt = 0; nt < 4; nt++) {
                unsigned b[2];
                int c0 = nw + nt * 8 + g;
                b[0] = *(const unsigned*)&Ks[c0 * 40 + kb + tig * 2];
                b[1] = *(const unsigned*)&Ks[c0 * 40 + kb + 8 + tig * 2];
                mma16(acc[nt], a, b);
            }
        }
        #pragma unroll
        for (int nt = 0; nt < 4; nt++) {
            int cc = nw + nt * 8 + tig * 2;
            Ss[mw + g][cc]         = acc[nt][0];
            Ss[mw + g][cc + 1]     = acc[nt][1];
            Ss[mw + g + 8][cc]     = acc[nt][2];
            Ss[mw + g + 8][cc + 1] = acc[nt][3];
        }
    }
    __syncthreads();

    // softmax rows (8 warps x 8 rows): write attn probs + bf16 P
    for (int rr = 0; rr < 8; rr++) {
        int i = wid * 8 + rr;
        float a0 = Ss[i][lane], a1 = Ss[i][lane + 32];
        float mx = fmaxf(a0, a1);
        #pragma unroll
        for (int o = 16; o; o >>= 1) mx = fmaxf(mx, __shfl_xor_sync(~0u, mx, o));
        float e0 = __expf(a0 - mx), e1 = __expf(a1 - mx);
        float sm = e0 + e1;
        #pragma unroll
        for (int o = 16; o; o >>= 1) sm += __shfl_xor_sync(~0u, sm, o);
        float inv = 1.f / sm;
        e0 *= inv; e1 *= inv;
        Ps[i * 72 + lane]      = __float2bfloat16(e0);
        Ps[i * 72 + lane + 32] = __float2bfloat16(e1);
        float* ao = attn_out + ((size_t)(w * 3 + h) * 64 + i) * 64;
        ao[lane] = e0; ao[lane + 32] = e1;
    }
    __syncthreads();

    // O = P @ V + LePE : warp computes 16 rows x 16 dims
    {
        int mw = (wid >> 1) * 16, nw = (wid & 1) * 16;
        float acc[2][4] = {};
        #pragma unroll
        for (int ks = 0; ks < 4; ks++) {
            int kb = ks * 16;
            unsigned a[4];
            a[0] = *(const unsigned*)&Ps[(mw + g)     * 72 + kb + tig * 2];
            a[1] = *(const unsigned*)&Ps[(mw + g + 8) * 72 + kb + tig * 2];
            a[2] = *(const unsigned*)&Ps[(mw + g)     * 72 + kb + 8 + tig * 2];
            a[3] = *(const unsigned*)&Ps[(mw + g + 8) * 72 + kb + 8 + tig * 2];
            #pragma unroll
            for (int nt = 0; nt < 2; nt++) {
                unsigned b[2];
                int c0 = nw + nt * 8 + g;
                b[0] = *(const unsigned*)&Vt[c0 * 72 + kb + tig * 2];
                b[1] = *(const unsigned*)&Vt[c0 * 72 + kb + 8 + tig * 2];
                mma16(acc[nt], a, b);
            }
        }
        #pragma unroll
        for (int nt = 0; nt < 2; nt++) {
            #pragma unroll
            for (int half = 0; half < 2; half++) {
                int t = mw + g + half * 8;
                int gy = t >> 3, gx = t & 7;
                #pragma unroll
                for (int e = 0; e < 2; e++) {
                    int d = nw + nt * 8 + tig * 2 + e;
                    int c = h * 32 + d;
                    float lp = bl[c];
                    #pragma unroll
                    for (int dy = -1; dy <= 1; dy++) {
                        int yy = gy + dy;
                        if (yy < 0 || yy > 7) continue;
                        #pragma unroll
                        for (int dxk = -1; dxk <= 1; dxk++) {
                            int xx = gx + dxk;
                            if (xx < 0 || xx > 7) continue;
                            lp += __bfloat162float(Vt[d * 72 + yy * 8 + xx]) *
                                  wl[c * 9 + (dy + 1) * 3 + (dxk + 1)];
                        }
                    }
                    obuf[(size_t)(w * 64 + t) * C_N + c] =
                        acc[nt][half * 2 + e] + lp;
                }
            }
        }
    }
}

// ---------------- launch ----------------
extern "C" void kernel_launch(void* const* d_in, const int* in_sizes, int n_in,
                              void* d_out, int out_size) {
    const float* x      = (const float*)d_in[0];
    const float* w_qkv  = (const float*)d_in[1];
    const float* b_qkv  = (const float*)d_in[2];
    const float* w_lepe = (const float*)d_in[3];
    const float* b_lepe = (const float*)d_in[4];
    const float* w_proj = (const float*)d_in[5];
    const float* b_proj = (const float*)d_in[6];
    const float* g1     = (const float*)d_in[7];
    const float* bt1    = (const float*)d_in[8];
    const float* g2     = (const float*)d_in[9];
    const float* bt2    = (const float*)d_in[10];
    const float* w_fc1  = (const float*)d_in[11];
    const float* b_fc1  = (const float*)d_in[12];
    const float* w_fc2  = (const float*)d_in[13];
    const float* b_fc2  = (const float*)d_in[14];

    float* out0 = (float*)d_out;

    float *pqkv, *po, *px1, *pfb;
    cudaGetSymbolAddress((void**)&pqkv, g_qkv);
    cudaGetSymbolAddress((void**)&po,   g_o);
    cudaGetSymbolAddress((void**)&px1,  g_x1);
    cudaGetSymbolAddress((void**)&pfb,  g_attn_fb);

    __nv_bfloat16 *pwqkv, *pwproj;
    cudaGetSymbolAddress((void**)&pwqkv,  g_wqkv_bf);
    cudaGetSymbolAddress((void**)&pwproj, g_wproj_bf);

    float* attn_out = (out_size >= OUT0_ELEMS + ATTN_ELEMS)
                        ? (out0 + OUT0_ELEMS) : pfb;

    cudaFuncSetAttribute(mlp_kernel,
                         cudaFuncAttributeMaxDynamicSharedMemorySize, 89600);

    // 0. precompute bf16 weights (runs each replay; deterministic, ~3us)
    prep_weights<<<432, 256>>>(w_qkv, w_proj, w_fc1, w_fc2);

    // 1. LN1 + QKV
    gemm96<true, 0><<<dim3(3, T_N / 128), 256>>>(
        x, pwqkv, b_qkv, nullptr, g1, bt1, pqkv, 288);

    // 2. attention + lepe (+ attn probs)
    attn_kernel<<<dim3(NW_N, NH_N), 256>>>(pqkv, w_lepe, b_lepe, po, attn_out);

    // 3. proj + window-reverse scatter + residual(x) -> x1
    gemm96<false, 1><<<dim3(1, T_N / 128), 256>>>(
        po, pwproj, b_proj, x, nullptr, nullptr, px1, 96);

    // 4. fused MLP: LN2 + FC1 + GELU + FC2 + residual -> out
    mlp_kernel<<<T_N / 128, 256, 89600>>>(px1, b_fc1, b_fc2, g2, bt2, out0);
}

// round 6
// speedup vs baseline: 4.0178x; 1.0736x over previous
#include <cuda_runtime.h>
#include <cuda_bf16.h>
#include <math.h>

// ---------------- problem constants ----------------
#define B_N   32
#define L_N   4096
#define C_N   96
#define GG_N  64
#define NW_N  2048
#define T_N   131072
#define HID_N 384

#define OUT0_ELEMS (T_N * C_N)
#define ATTN_ELEMS (NW_N * 3 * GG_N * GG_N)

#define SCALE_F 0.17677669529663687f  // 32^-0.5

// ---------------- scratch ----------------
__device__ float g_x1[T_N * C_N];        // x + proj, token-major
__device__ float g_attn_fb[ATTN_ELEMS];  // fallback sink for attn probs

// precomputed bf16 weights, [n][k] layout, k padded to 100
__device__ __nv_bfloat16 g_wqkv_bf[288 * 100];
__device__ __nv_bfloat16 g_wproj_bf[96 * 100];
__device__ __nv_bfloat16 g_w1_bf[384 * 100];
__device__ __nv_bfloat16 g_w2_bf[4 * 96 * 100];  // [chunk][n][k]

#define QKV_E  (288 * 96)
#define PROJ_E (96 * 96)
#define W1_E   (384 * 96)
#define W2_E   (4 * 96 * 96)

__global__ void prep_weights(const float* __restrict__ wqkv,
                             const float* __restrict__ wproj,
                             const float* __restrict__ w1,
                             const float* __restrict__ w2) {
    int i = blockIdx.x * 256 + threadIdx.x;
    if (i < QKV_E) {
        int n = i / 96, k = i - n * 96;
        g_wqkv_bf[n * 100 + k] = __float2bfloat16(wqkv[(size_t)k * 288 + n]);
        return;
    }
    i -= QKV_E;
    if (i < PROJ_E) {
        int n = i / 96, k = i - n * 96;
        g_wproj_bf[n * 100 + k] = __float2bfloat16(wproj[(size_t)k * 96 + n]);
        return;
    }
    i -= PROJ_E;
    if (i < W1_E) {
        int n = i / 96, k = i - n * 96;
        g_w1_bf[n * 100 + k] = __float2bfloat16(w1[(size_t)k * 384 + n]);
        return;
    }
    i -= W1_E;
    if (i < W2_E) {
        int c = i / 9216, r = i - c * 9216;
        int n = r / 96, k = r - n * 96;
        g_w2_bf[c * 9600 + n * 100 + k] =
            __float2bfloat16(w2[(size_t)(c * 96 + k) * 96 + n]);
    }
}

__device__ __forceinline__ int win2tok(int m) {
    int w = m >> 6, t = m & 63;
    int b = w >> 6, rem = w & 63;
    int hy = rem >> 3, wx = rem & 7;
    int gy = t >> 3,  gx = t & 7;
    return b * L_N + (hy * 8 + gy) * 64 + (wx * 8 + gx);
}

__device__ __forceinline__ void mma16(float* c, const unsigned* a, const unsigned* b) {
    asm volatile(
        "mma.sync.aligned.m16n8k16.row.col.f32.bf16.bf16.f32 "
        "{%0,%1,%2,%3}, {%4,%5,%6,%7}, {%8,%9}, {%0,%1,%2,%3};\n"
        : "+f"(c[0]), "+f"(c[1]), "+f"(c[2]), "+f"(c[3])
        : "r"(a[0]), "r"(a[1]), "r"(a[2]), "r"(a[3]), "r"(b[0]), "r"(b[1]));
}

// warp computes LN of one 96-wide row; writes bf16 into smem row (stride 100)
__device__ __forceinline__ void ln_row_to_smem(const float* __restrict__ xr,
                                               const float* __restrict__ g,
                                               const float* __restrict__ b,
                                               __nv_bfloat16* __restrict__ dst,
                                               int lane) {
    float v0 = xr[lane], v1 = xr[lane + 32], v2 = xr[lane + 64];
    float s = v0 + v1 + v2;
    #pragma unroll
    for (int o = 16; o; o >>= 1) s += __shfl_xor_sync(~0u, s, o);
    float m = s * (1.f / 96.f);
    float d0 = v0 - m, d1 = v1 - m, d2 = v2 - m;
    float q = d0 * d0 + d1 * d1 + d2 * d2;
    #pragma unroll
    for (int o = 16; o; o >>= 1) q += __shfl_xor_sync(~0u, q, o);
    float r = rsqrtf(q * (1.f / 96.f) + 1e-5f);
    dst[lane]      = __float2bfloat16(d0 * r * g[lane]      + b[lane]);
    dst[lane + 32] = __float2bfloat16(d1 * r * g[lane + 32] + b[lane + 32]);
    dst[lane + 64] = __float2bfloat16(d2 * r * g[lane + 64] + b[lane + 64]);
}

// ---------------- window megakernel: LN1+QKV+attn+LePE+proj+residual ------
// smem layout (bytes):
#define SM_U    0        // 19200: weight stage (96x100 bf16) / Ss fp32 (64x66)
#define SM_QS   19200    // 12800: Q scaled+biased, [t][c] bf16 stride 100
#define SM_KS   32000    // 12800: K, [t][c] stride 100
#define SM_VT   44800    // 13824: V^T, [c][t] bf16 stride 72
#define SM_PS   58624    // 12800: As (LN x, stride 100) then Ps (stride 72)
#define SM_OS   71424    // 12800: attn out + lepe, [t][c] bf16 stride 100
#define SM_XS   84224    // 24576: x window rows fp32, [t][c] stride 96
#define SM_MEGA 108800

__global__ __launch_bounds__(256)
void mega_kernel(const float* __restrict__ x,
                 const float* __restrict__ bqkv,
                 const float* __restrict__ wl,
                 const float* __restrict__ bl,
                 const float* __restrict__ bproj,
                 const float* __restrict__ lng,
                 const float* __restrict__ lnb,
                 float* __restrict__ x1,
                 float* __restrict__ attn_out) {
    extern __shared__ char smraw[];
    __nv_bfloat16* U  = (__nv_bfloat16*)(smraw + SM_U);
    float*         Ssm = (float*)(smraw + SM_U);
    __nv_bfloat16* Qs = (__nv_bfloat16*)(smraw + SM_QS);
    __nv_bfloat16* Ks = (__nv_bfloat16*)(smraw + SM_KS);
    __nv_bfloat16* Vt = (__nv_bfloat16*)(smraw + SM_VT);
    __nv_bfloat16* As = (__nv_bfloat16*)(smraw + SM_PS);
    __nv_bfloat16* Ps = (__nv_bfloat16*)(smraw + SM_PS);
    __nv_bfloat16* Os = (__nv_bfloat16*)(smraw + SM_OS);
    float*         Xs = (float*)(smraw + SM_XS);

    int w = blockIdx.x;
    int tid = threadIdx.x, lane = tid & 31, wid = tid >> 5;
    int g = lane >> 2, tig = lane & 3;

    // ---- phase 0: load x window rows, LN1 -> As (bf16), x -> Xs (fp32) ----
    #pragma unroll
    for (int r = 0; r < 8; r++) {
        int t = wid * 8 + r;
        const float* xr = x + (size_t)win2tok(w * 64 + t) * 96;
        float v0 = xr[lane], v1 = xr[lane + 32], v2 = xr[lane + 64];
        Xs[t * 96 + lane]      = v0;
        Xs[t * 96 + lane + 32] = v1;
        Xs[t * 96 + lane + 64] = v2;
        float s = v0 + v1 + v2;
        #pragma unroll
        for (int o = 16; o; o >>= 1) s += __shfl_xor_sync(~0u, s, o);
        float m = s * (1.f / 96.f);
        float d0 = v0 - m, d1 = v1 - m, d2 = v2 - m;
        float q = d0 * d0 + d1 * d1 + d2 * d2;
        #pragma unroll
        for (int o = 16; o; o >>= 1) q += __shfl_xor_sync(~0u, q, o);
        float rr = rsqrtf(q * (1.f / 96.f) + 1e-5f);
        As[t * 100 + lane]      = __float2bfloat16(d0 * rr * lng[lane]      + lnb[lane]);
        As[t * 100 + lane + 32] = __float2bfloat16(d1 * rr * lng[lane + 32] + lnb[lane + 32]);
        As[t * 100 + lane + 64] = __float2bfloat16(d2 * rr * lng[lane + 64] + lnb[lane + 64]);
    }
    __syncthreads();

    int mw = (wid >> 1) * 16;

    // ---- phase 1: QKV = As @ Wqkv (+bias), 3 segments of 96 cols ----
    #pragma unroll
    for (int seg = 0; seg < 3; seg++) {
        {
            const int4* src = (const int4*)(g_wqkv_bf + (size_t)seg * 9600);
            int4* dst = (int4*)U;
            #pragma unroll
            for (int e = 0; e < 5; e++) {
                int i = e * 256 + tid;
                if (i < 1200) dst[i] = src[i];
            }
        }
        __syncthreads();

        int nw = (wid & 1) * 48;
        float acc[6][4] = {};
        #pragma unroll
        for (int ks = 0; ks < 6; ks++) {
            int kb = ks * 16;
            unsigned a[4];
            a[0] = *(const unsigned*)&As[(mw + g)     * 100 + kb + tig * 2];
            a[1] = *(const unsigned*)&As[(mw + g + 8) * 100 + kb + tig * 2];
            a[2] = *(const unsigned*)&As[(mw + g)     * 100 + kb + 8 + tig * 2];
            a[3] = *(const unsigned*)&As[(mw + g + 8) * 100 + kb + 8 + tig * 2];
            #pragma unroll
            for (int nt = 0; nt < 6; nt++) {
                unsigned b[2];
                int c0 = nw + nt * 8 + g;
                b[0] = *(const unsigned*)&U[c0 * 100 + kb + tig * 2];
                b[1] = *(const unsigned*)&U[c0 * 100 + kb + 8 + tig * 2];
                mma16(acc[nt], a, b);
            }
        }
        #pragma unroll
        for (int nt = 0; nt < 6; nt++) {
            #pragma unroll
            for (int half = 0; half < 2; half++) {
                int t = mw + g + half * 8;
                int c = nw + nt * 8 + tig * 2;
                float v0 = acc[nt][half * 2 + 0] + bqkv[seg * 96 + c];
                float v1 = acc[nt][half * 2 + 1] + bqkv[seg * 96 + c + 1];
                if (seg == 0) {
                    *(__nv_bfloat162*)&Qs[t * 100 + c] =
                        __floats2bfloat162_rn(v0 * SCALE_F, v1 * SCALE_F);
                } else if (seg == 1) {
                    *(__nv_bfloat162*)&Ks[t * 100 + c] =
                        __floats2bfloat162_rn(v0, v1);
                } else {
                    Vt[c * 72 + t]       = __float2bfloat16(v0);
                    Vt[(c + 1) * 72 + t] = __float2bfloat16(v1);
                }
            }
        }
        __syncthreads();
    }

    // ---- phase 2: per-head attention ----
    #pragma unroll
    for (int h = 0; h < 3; h++) {
        int h32 = h * 32;
        // S = Qscaled @ K^T  (warp: 16 rows x 32 cols)
        {
            int nw = (wid & 1) * 32;
            float acc[4][4] = {};
            #pragma unroll
            for (int ks = 0; ks < 2; ks++) {
                int kb = h32 + ks * 16;
                unsigned a[4];
                a[0] = *(const unsigned*)&Qs[(mw + g)     * 100 + kb + tig * 2];
                a[1] = *(const unsigned*)&Qs[(mw + g + 8) * 100 + kb + tig * 2];
                a[2] = *(const unsigned*)&Qs[(mw + g)     * 100 + kb + 8 + tig * 2];
                a[3] = *(const unsigned*)&Qs[(mw + g + 8) * 100 + kb + 8 + tig * 2];
                #pragma unroll
                for (int nt = 0; nt < 4; nt++) {
                    unsigned b[2];
                    int c0 = nw + nt * 8 + g;
                    b[0] = *(const unsigned*)&Ks[c0 * 100 + kb + tig * 2];
                    b[1] = *(const unsigned*)&Ks[c0 * 100 + kb + 8 + tig * 2];
                    mma16(acc[nt], a, b);
                }
            }
            #pragma unroll
            for (int nt = 0; nt < 4; nt++) {
                int cc = nw + nt * 8 + tig * 2;
                Ssm[(mw + g)     * 66 + cc]     = acc[nt][0];
                Ssm[(mw + g)     * 66 + cc + 1] = acc[nt][1];
                Ssm[(mw + g + 8) * 66 + cc]     = acc[nt][2];
                Ssm[(mw + g + 8) * 66 + cc + 1] = acc[nt][3];
            }
        }
        __syncthreads();

        // softmax (8 warps x 8 rows) -> probs gmem + Ps bf16
        #pragma unroll
        for (int rr2 = 0; rr2 < 8; rr2++) {
            int i = wid * 8 + rr2;
            float a0 = Ssm[i * 66 + lane], a1 = Ssm[i * 66 + lane + 32];
            float mx = fmaxf(a0, a1);
            #pragma unroll
            for (int o = 16; o; o >>= 1) mx = fmaxf(mx, __shfl_xor_sync(~0u, mx, o));
            float e0 = __expf(a0 - mx), e1 = __expf(a1 - mx);
            float sm = e0 + e1;
            #pragma unroll
            for (int o = 16; o; o >>= 1) sm += __shfl_xor_sync(~0u, sm, o);
            float inv = 1.f / sm;
            e0 *= inv; e1 *= inv;
            Ps[i * 72 + lane]      = __float2bfloat16(e0);
            Ps[i * 72 + lane + 32] = __float2bfloat16(e1);
            float* ao = attn_out + ((size_t)(w * 3 + h) * 64 + i) * 64;
            ao[lane] = e0; ao[lane + 32] = e1;
        }
        __syncthreads();

        // O = P @ V + LePE -> Os cols [h32, h32+32)  (warp: 16 rows x 16 d)
        {
            int d0 = h32 + (wid & 1) * 16;
            float acc[2][4] = {};
            #pragma unroll
            for (int ks = 0; ks < 4; ks++) {
                int kb = ks * 16;
                unsigned a[4];
                a[0] = *(const unsigned*)&Ps[(mw + g)     * 72 + kb + tig * 2];
                a[1] = *(const unsigned*)&Ps[(mw + g + 8) * 72 + kb + tig * 2];
                a[2] = *(const unsigned*)&Ps[(mw + g)     * 72 + kb + 8 + tig * 2];
                a[3] = *(const unsigned*)&Ps[(mw + g + 8) * 72 + kb + 8 + tig * 2];
                #pragma unroll
                for (int nt = 0; nt < 2; nt++) {
                    unsigned b[2];
                    int c0 = d0 + nt * 8 + g;
                    b[0] = *(const unsigned*)&Vt[c0 * 72 + kb + tig * 2];
                    b[1] = *(const unsigned*)&Vt[c0 * 72 + kb + 8 + tig * 2];
                    mma16(acc[nt], a, b);
                }
            }
            #pragma unroll
            for (int nt = 0; nt < 2; nt++) {
                #pragma unroll
                for (int half = 0; half < 2; half++) {
                    int t = mw + g + half * 8;
                    int gy = t >> 3, gx = t & 7;
                    #pragma unroll
                    for (int e = 0; e < 2; e++) {
                        int d = d0 + nt * 8 + tig * 2 + e;  // global channel
                        float lp = bl[d];
                        #pragma unroll
                        for (int dy = -1; dy <= 1; dy++) {
                            int yy = gy + dy;
                            if (yy < 0 || yy > 7) continue;
                            #pragma unroll
                            for (int dxk = -1; dxk <= 1; dxk++) {
                                int xx = gx + dxk;
                                if (xx < 0 || xx > 7) continue;
                                lp += __bfloat162float(Vt[d * 72 + yy * 8 + xx]) *
                                      wl[d * 9 + (dy + 1) * 3 + (dxk + 1)];
                            }
                        }
                        Os[t * 100 + d] =
                            __float2bfloat16(acc[nt][half * 2 + e] + lp);
                    }
                }
            }
        }
        __syncthreads();
    }

    // ---- phase 3: proj + residual ----
    {
        const int4* src = (const int4*)g_wproj_bf;
        int4* dst = (int4*)U;
        #pragma unroll
        for (int e = 0; e < 5; e++) {
            int i = e * 256 + tid;
            if (i < 1200) dst[i] = src[i];
        }
    }
    __syncthreads();
    {
        int nw = (wid & 1) * 48;
        float acc[6][4] = {};
        #pragma unroll
        for (int ks = 0; ks < 6; ks++) {
            int kb = ks * 16;
            unsigned a[4];
            a[0] = *(const unsigned*)&Os[(mw + g)     * 100 + kb + tig * 2];
            a[1] = *(const unsigned*)&Os[(mw + g + 8) * 100 + kb + tig * 2];
            a[2] = *(const unsigned*)&Os[(mw + g)     * 100 + kb + 8 + tig * 2];
            a[3] = *(const unsigned*)&Os[(mw + g + 8) * 100 + kb + 8 + tig * 2];
            #pragma unroll
            for (int nt = 0; nt < 6; nt++) {
                unsigned b[2];
                int c0 = nw + nt * 8 + g;
                b[0] = *(const unsigned*)&U[c0 * 100 + kb + tig * 2];
                b[1] = *(const unsigned*)&U[c0 * 100 + kb + 8 + tig * 2];
                mma16(acc[nt], a, b);
            }
        }
        #pragma unroll
        for (int half = 0; half < 2; half++) {
            int t = mw + g + half * 8;
            int tok = win2tok(w * 64 + t);
            #pragma unroll
            for (int nt = 0; nt < 6; nt++) {
                int c = nw + nt * 8 + tig * 2;
                float v0 = acc[nt][half * 2 + 0] + bproj[c]     + Xs[t * 96 + c];
                float v1 = acc[nt][half * 2 + 1] + bproj[c + 1] + Xs[t * 96 + c + 1];
                *(float2*)(x1 + (size_t)tok * 96 + c) = make_float2(v0, v1);
            }
        }
    }
}

// ---------------- fused MLP: LN2 + FC1 + GELU + FC2 + residual ------------
__global__ __launch_bounds__(256)
void mlp_kernel(const float* __restrict__ x1,
                const float* __restrict__ b1, const float* __restrict__ b2,
                const float* __restrict__ lng, const float* __restrict__ lnb,
                float* __restrict__ out) {
    extern __shared__ __nv_bfloat16 sm[];
    __nv_bfloat16* As = sm;                 // 128*100 LN2 activations
    __nv_bfloat16* Hs = sm + 12800;         // 128*100 gelu hidden chunk
    __nv_bfloat16* B1 = sm + 25600;         // 96*100  W1 chunk [n][k]
    __nv_bfloat16* B2 = sm + 35200;         // 96*100  W2 chunk [n][k]

    int tid = threadIdx.x, lane = tid & 31, wid = tid >> 5;
    int g = lane >> 2, tig = lane & 3;
    int m0 = blockIdx.x * 128;
    int wm = wid >> 1, wn = wid & 1;
    int mw = wm * 32, nw = wn * 48;

    #pragma unroll
    for (int r = 0; r < 16; r++) {
        int row = wid * 16 + r;
        ln_row_to_smem(x1 + (size_t)(m0 + row) * 96, lng, lnb, As + row * 100, lane);
    }

    float acc2[2][6][4] = {};
    for (int c = 0; c < 4; c++) {
        {
            const int4* s1 = (const int4*)(g_w1_bf + (size_t)c * 9600);
            const int4* s2 = (const int4*)(g_w2_bf + (size_t)c * 9600);
            int4* d1 = (int4*)B1;
            int4* d2 = (int4*)B2;
            #pragma unroll
            for (int e = 0; e < 5; e++) {
                int i = e * 256 + tid;
                if (i < 1200) { d1[i] = s1[i]; d2[i] = s2[i]; }
            }
        }
        __syncthreads();

        float accH[2][6][4] = {};
        #pragma unroll
        for (int ks = 0; ks < 6; ks++) {
            int kb = ks * 16;
            unsigned a[2][4], b[6][2];
            #pragma unroll
            for (int mt = 0; mt < 2; mt++) {
                int r = mw + mt * 16;
                a[mt][0] = *(const unsigned*)&As[(r + g)     * 100 + kb + tig * 2];
                a[mt][1] = *(const unsigned*)&As[(r + g + 8) * 100 + kb + tig * 2];
                a[mt][2] = *(const unsigned*)&As[(r + g)     * 100 + kb + 8 + tig * 2];
                a[mt][3] = *(const unsigned*)&As[(r + g + 8) * 100 + kb + 8 + tig * 2];
            }
            #pragma unroll
            for (int nt = 0; nt < 6; nt++) {
                int cc = nw + nt * 8 + g;
                b[nt][0] = *(const unsigned*)&B1[cc * 100 + kb + tig * 2];
                b[nt][1] = *(const unsigned*)&B1[cc * 100 + kb + 8 + tig * 2];
            }
            #pragma unroll
            for (int mt = 0; mt < 2; mt++)
                #pragma unroll
                for (int nt = 0; nt < 6; nt++)
                    mma16(accH[mt][nt], a[mt], b[nt]);
        }
        #pragma unroll
        for (int mt = 0; mt < 2; mt++) {
            #pragma unroll
            for (int half = 0; half < 2; half++) {
                int row = mw + mt * 16 + g + half * 8;
                #pragma unroll
                for (int nt = 0; nt < 6; nt++) {
                    int col = nw + nt * 8 + tig * 2;
                    float v0 = accH[mt][nt][half * 2 + 0] + b1[c * 96 + col];
                    float v1 = accH[mt][nt][half * 2 + 1] + b1[c * 96 + col + 1];
                    v0 = 0.5f * v0 * (1.f + erff(v0 * 0.70710678118f));
                    v1 = 0.5f * v1 * (1.f + erff(v1 * 0.70710678118f));
                    *(__nv_bfloat162*)&Hs[row * 100 + col] = __floats2bfloat162_rn(v0, v1);
                }
            }
        }
        __syncthreads();

        #pragma unroll
        for (int ks = 0; ks < 6; ks++) {
            int kb = ks * 16;
            unsigned a[2][4], b[6][2];
            #pragma unroll
            for (int mt = 0; mt < 2; mt++) {
                int r = mw + mt * 16;
                a[mt][0] = *(const unsigned*)&Hs[(r + g)     * 100 + kb + tig * 2];
                a[mt][1] = *(const unsigned*)&Hs[(r + g + 8) * 100 + kb + tig * 2];
                a[mt][2] = *(const unsigned*)&Hs[(r + g)     * 100 + kb + 8 + tig * 2];
                a[mt][3] = *(const unsigned*)&Hs[(r + g + 8) * 100 + kb + 8 + tig * 2];
            }
            #pragma unroll
            for (int nt = 0; nt < 6; nt++) {
                int cc = nw + nt * 8 + g;
                b[nt][0] = *(const unsigned*)&B2[cc * 100 + kb + tig * 2];
                b[nt][1] = *(const unsigned*)&B2[cc * 100 + kb + 8 + tig * 2];
            }
            #pragma unroll
            for (int mt = 0; mt < 2; mt++)
                #pragma unroll
                for (int nt = 0; nt < 6; nt++)
                    mma16(acc2[mt][nt], a[mt], b[nt]);
        }
        __syncthreads();
    }

    #pragma unroll
    for (int mt = 0; mt < 2; mt++) {
        #pragma unroll
        for (int half = 0; half < 2; half++) {
            int row = m0 + mw + mt * 16 + g + half * 8;
            #pragma unroll
            for (int nt = 0; nt < 6; nt++) {
                int col = nw + nt * 8 + tig * 2;
                const float2 r2 = *(const float2*)(x1 + (size_t)row * 96 + col);
                float v0 = acc2[mt][nt][half * 2 + 0] + b2[col]     + r2.x;
                float v1 = acc2[mt][nt][half * 2 + 1] + b2[col + 1] + r2.y;
                *(float2*)(out + (size_t)row * 96 + col) = make_float2(v0, v1);
            }
        }
    }
}

// ---------------- launch ----------------
extern "C" void kernel_launch(void* const* d_in, const int* in_sizes, int n_in,
                              void* d_out, int out_size) {
    const float* x      = (const float*)d_in[0];
    const float* w_qkv  = (const float*)d_in[1];
    const float* b_qkv  = (const float*)d_in[2];
    const float* w_lepe = (const float*)d_in[3];
    const float* b_lepe = (const float*)d_in[4];
    const float* w_proj = (const float*)d_in[5];
    const float* b_proj = (const float*)d_in[6];
    const float* g1     = (const float*)d_in[7];
    const float* bt1    = (const float*)d_in[8];
    const float* g2     = (const float*)d_in[9];
    const float* bt2    = (const float*)d_in[10];
    const float* w_fc1  = (const float*)d_in[11];
    const float* b_fc1  = (const float*)d_in[12];
    const float* w_fc2  = (const float*)d_in[13];
    const float* b_fc2  = (const float*)d_in[14];

    float* out0 = (float*)d_out;

    float *px1, *pfb;
    cudaGetSymbolAddress((void**)&px1, g_x1);
    cudaGetSymbolAddress((void**)&pfb, g_attn_fb);

    float* attn_out = (out_size >= OUT0_ELEMS + ATTN_ELEMS)
                        ? (out0 + OUT0_ELEMS) : pfb;

    cudaFuncSetAttribute(mega_kernel,
                         cudaFuncAttributeMaxDynamicSharedMemorySize, SM_MEGA);
    cudaFuncSetAttribute(mlp_kernel,
                         cudaFuncAttributeMaxDynamicSharedMemorySize, 89600);

    // 0. precompute bf16 weights
    prep_weights<<<432, 256>>>(w_qkv, w_proj, w_fc1, w_fc2);

    // 1. window megakernel: LN1 + QKV + attention + LePE + proj + residual
    mega_kernel<<<NW_N, 256, SM_MEGA>>>(x, b_qkv, w_lepe, b_lepe, b_proj,
                                        g1, bt1, px1, attn_out);

    // 2. fused MLP: LN2 + FC1 + GELU + FC2 + residual -> out
    mlp_kernel<<<T_N / 128, 256, 89600>>>(px1, b_fc1, b_fc2, g2, bt2, out0);
}